// round 15
// baseline (speedup 1.0000x reference)
#include <cuda_runtime.h>
#include <cuda_bf16.h>
#include <math.h>
#include <stdint.h>

#define DM   2048
#define NH   16
#define DKH  128
#define NB   4
#define SEQ  2048
#define MTOT (NB*SEQ)   // 8192

// hybrid split: blocks y < HMMA_BLKS use tensor path, rest fp32 FFMA path
#define HMMA_BLKS 42

typedef unsigned long long ull;
typedef __nv_bfloat16 bf16;

// ---- packed f32x2 helpers ---------------------------------------------------
__device__ __forceinline__ ull dup_f(float x) {
    ull d; asm("mov.b64 %0, {%1, %1};" : "=l"(d) : "f"(x)); return d;
}
__device__ __forceinline__ void fma2(ull& d, ull a, ull b) {
    asm("fma.rn.f32x2 %0, %1, %2, %0;" : "+l"(d) : "l"(a), "l"(b));
}
__device__ __forceinline__ void mul2(ull& d, ull a) {
    asm("mul.rn.f32x2 %0, %0, %1;" : "+l"(d) : "l"(a));
}
__device__ __forceinline__ float2 unpk(ull v) {
    float2 f; asm("mov.b64 {%0, %1}, %2;" : "=f"(f.x), "=f"(f.y) : "l"(v)); return f;
}

// ---- HMMA helpers -----------------------------------------------------------
__device__ __forceinline__ uint32_t smem_u32(const void* p) {
    uint32_t a;
    asm("{ .reg .u64 t; cvta.to.shared.u64 t, %1; cvt.u32.u64 %0, t; }"
        : "=r"(a) : "l"(p));
    return a;
}
__device__ __forceinline__ void ldsm4(uint32_t* r, uint32_t addr) {
    asm volatile("ldmatrix.sync.aligned.m8n8.x4.shared.b16 {%0,%1,%2,%3}, [%4];"
                 : "=r"(r[0]), "=r"(r[1]), "=r"(r[2]), "=r"(r[3]) : "r"(addr));
}
__device__ __forceinline__ void mma16816(float* d, const uint32_t* a,
                                         uint32_t b0, uint32_t b1) {
    asm volatile(
        "mma.sync.aligned.m16n8k16.row.col.f32.bf16.bf16.f32 "
        "{%0,%1,%2,%3}, {%4,%5,%6,%7}, {%8,%9}, {%0,%1,%2,%3};"
        : "+f"(d[0]), "+f"(d[1]), "+f"(d[2]), "+f"(d[3])
        : "r"(a[0]), "r"(a[1]), "r"(a[2]), "r"(a[3]), "r"(b0), "r"(b1));
}
__device__ __forceinline__ void cp16(uint32_t dst, const void* src) {
    asm volatile("cp.async.cg.shared.global [%0], [%1], 16;"
                 :: "r"(dst), "l"(src));
}
__device__ __forceinline__ void cp_commit() {
    asm volatile("cp.async.commit_group;" ::: "memory");
}
template<int N> __device__ __forceinline__ void cp_wait() {
    asm volatile("cp.async.wait_group %0;" :: "n"(N) : "memory");
}
__device__ __forceinline__ uint32_t tile_off(int r, int c) {
    return (uint32_t)(r * 64 + ((c ^ ((r >> 1) & 3)) << 4));
}

// ---- scratch ----------------------------------------------------------------
__device__ float g_q[(size_t)NB*NH*SEQ*DKH];
__device__ float g_k[(size_t)NB*NH*SEQ*DKH];
__device__ float g_v[(size_t)NB*NH*SEQ*DKH];
__device__ float g_att[(size_t)MTOT*DM];
__device__ bf16 g_ah[(size_t)MTOT*DM];
__device__ bf16 g_al[(size_t)MTOT*DM];
__device__ bf16 g_wh[(size_t)DM*DM];
__device__ bf16 g_wl[(size_t)DM*DM];

// ---------------------------------------------------------------------------
__global__ __launch_bounds__(256)
void split_bf16(const float* __restrict__ in, bf16* __restrict__ hi,
                bf16* __restrict__ lo, int n4) {
    int i = blockIdx.x * 256 + threadIdx.x;
    if (i >= n4) return;
    float4 v = *(const float4*)(in + (size_t)i * 4);
    float vv[4] = {v.x, v.y, v.z, v.w};
    bf16 h[4], l[4];
#pragma unroll
    for (int j = 0; j < 4; j++) {
        h[j] = __float2bfloat16(vv[j]);
        l[j] = __float2bfloat16(vv[j] - __bfloat162float(h[j]));
    }
    *(uint2*)(hi + (size_t)i * 4) = *(uint2*)h;
    *(uint2*)(lo + (size_t)i * 4) = *(uint2*)l;
}

// ---------------------------------------------------------------------------
// Hybrid GEMM: C[8192,2048] = A @ W^T.
// Blocks y < HMMA_BLKS: 3-term bf16 HMMA path (tensor pipe).
// Blocks y >= HMMA_BLKS: fp32 FFMA path from original operands (fma pipe).
// ---------------------------------------------------------------------------
#define STAGE_BYTES 32768
#define NSTAGE      3
#define GEMM_SMEM   (NSTAGE * STAGE_BYTES)   // 96KB (FFMA path uses first 16KB)
#define NKC         (DM / 32)                // 64

template<int HEAD_LAYOUT>
__global__ __launch_bounds__(256, 2)
void gemm_hybrid(const float* __restrict__ Af, const float* __restrict__ Wf,
                 const bf16* __restrict__ Ah, const bf16* __restrict__ Al,
                 const bf16* __restrict__ Wh, const bf16* __restrict__ Wl,
                 float* __restrict__ C) {
    extern __shared__ char smg[];
    const int tid = threadIdx.x;
    const int bn  = blockIdx.x;
    const int bm  = blockIdx.y * 128;

    if (blockIdx.y < HMMA_BLKS) {
        // ===================== HMMA path =====================
        const uint32_t smb = smem_u32(smg);
        const int wid = tid >> 5;
        const int lid = tid & 31;
        const int wm  = wid & 3;
        const int wn  = wid >> 2;

        const int ti    = tid >> 6;
        const int idx   = tid & 63;
        const int rbase = idx >> 2;
        const int lc    = idx & 3;
        const bf16* gsrc;
        {
            const bf16* s0 = Ah + (size_t)bm * DM;
            const bf16* s1 = Al + (size_t)bm * DM;
            const bf16* s2 = Wh + (size_t)(bn * 128) * DM;
            const bf16* s3 = Wl + (size_t)(bn * 128) * DM;
            gsrc = (ti == 0) ? s0 : (ti == 1) ? s1 : (ti == 2) ? s2 : s3;
        }
        const uint32_t tbase = (uint32_t)(ti * 8192);

        float acc[2][8][4];
#pragma unroll
        for (int a = 0; a < 2; a++)
#pragma unroll
            for (int b = 0; b < 8; b++)
#pragma unroll
                for (int c = 0; c < 4; c++) acc[a][b][c] = 0.f;

        const int a_row      = wm * 32;
        const int b_rowbase  = wn * 64 + (lid & 7) + ((lid >> 4) << 3);
        const int a_lane_row = (lid & 15);
        const int a_cadd     = (lid >> 4);
        const int b_cadd     = ((lid >> 3) & 1);

        auto issue = [&](int kc) {
            uint32_t sb = smb + (uint32_t)((kc % NSTAGE) * STAGE_BYTES) + tbase;
            const bf16* g = gsrc + kc * 32 + lc * 8;
#pragma unroll
            for (int lr = 0; lr < 8; lr++) {
                int row = rbase + lr * 16;
                cp16(sb + tile_off(row, lc), g + (size_t)row * DM);
            }
            cp_commit();
        };

        issue(0);
        issue(1);

        for (int kc = 0; kc < NKC; kc++) {
            if (kc + 2 < NKC) { issue(kc + 2); cp_wait<2>(); }
            else if (kc + 1 < NKC) cp_wait<1>();
            else cp_wait<0>();
            __syncthreads();

            const uint32_t sb = smb + (uint32_t)((kc % NSTAGE) * STAGE_BYTES);
#pragma unroll
            for (int ks = 0; ks < 2; ks++) {
                const int cbase = ks * 2;
                uint32_t ah[2][4], al[2][4];
#pragma unroll
                for (int mt = 0; mt < 2; mt++) {
                    int row = a_row + mt * 16 + a_lane_row;
                    uint32_t off = tile_off(row, cbase + a_cadd);
                    ldsm4(ah[mt], sb + 0 * 8192 + off);
                    ldsm4(al[mt], sb + 1 * 8192 + off);
                }
#pragma unroll
                for (int h = 0; h < 2; h++) {
                    uint32_t bh[2][4], bl[2][4];
#pragma unroll
                    for (int p = 0; p < 2; p++) {
                        int row = b_rowbase + (h * 2 + p) * 16;
                        uint32_t off = tile_off(row, cbase + b_cadd);
                        ldsm4(bh[p], sb + 2 * 8192 + off);
                        ldsm4(bl[p], sb + 3 * 8192 + off);
                    }
#pragma unroll
                    for (int mt = 0; mt < 2; mt++)
#pragma unroll
                        for (int nt = 0; nt < 4; nt++) {
                            int p = nt >> 1, rr = (nt & 1) * 2;
                            float* d = acc[mt][h * 4 + nt];
                            mma16816(d, ah[mt], bh[p][rr], bh[p][rr + 1]);
                            mma16816(d, ah[mt], bl[p][rr], bl[p][rr + 1]);
                            mma16816(d, al[mt], bh[p][rr], bh[p][rr + 1]);
                        }
                }
            }
            __syncthreads();
        }

        const int g = lid >> 2, t4 = lid & 3;
#pragma unroll
        for (int mt = 0; mt < 2; mt++) {
            int m0 = bm + wm * 32 + mt * 16 + g;
#pragma unroll
            for (int half = 0; half < 2; half++) {
                int m = m0 + half * 8;
                float* rowp;
                if (HEAD_LAYOUT) {
                    int b_ = m >> 11, s_ = m & (SEQ - 1);
                    rowp = C + (((size_t)(b_ * NH + bn) * SEQ + s_) * DKH);
                } else {
                    rowp = C + (size_t)m * DM + bn * 128;
                }
#pragma unroll
                for (int j = 0; j < 8; j++) {
                    int n = wn * 64 + j * 8 + t4 * 2;
                    *(float2*)(rowp + n) = make_float2(acc[mt][j][half * 2],
                                                       acc[mt][j][half * 2 + 1]);
                }
            }
        }
    } else {
        // ===================== FFMA (fp32) path =====================
        float* As = (float*)smg;          // [16][128]
        float* Bs = As + 16 * 128;        // [16][128]
        const int ty = tid >> 4;
        const int tx = tid & 15;

        float acc[8][8];
#pragma unroll
        for (int i = 0; i < 8; i++)
#pragma unroll
            for (int j = 0; j < 8; j++) acc[i][j] = 0.f;

        for (int k0 = 0; k0 < DM; k0 += 16) {
#pragma unroll
            for (int i = 0; i < 2; i++) {
                int f = tid * 2 + i;
                int r = f >> 2;
                int c = (f & 3) << 2;
                float4 a = *(const float4*)(Af + (size_t)(bm + r) * DM + k0 + c);
                As[(c + 0) * 128 + r] = a.x; As[(c + 1) * 128 + r] = a.y;
                As[(c + 2) * 128 + r] = a.z; As[(c + 3) * 128 + r] = a.w;
                float4 b = *(const float4*)(Wf + (size_t)(bn * 128 + r) * DM + k0 + c);
                Bs[(c + 0) * 128 + r] = b.x; Bs[(c + 1) * 128 + r] = b.y;
                Bs[(c + 2) * 128 + r] = b.z; Bs[(c + 3) * 128 + r] = b.w;
            }
            __syncthreads();
#pragma unroll
            for (int k = 0; k < 16; k++) {
                float a[8], b[8];
                *(float4*)&a[0] = *(const float4*)&As[k * 128 + ty * 8];
                *(float4*)&a[4] = *(const float4*)&As[k * 128 + ty * 8 + 4];
                *(float4*)&b[0] = *(const float4*)&Bs[k * 128 + tx * 8];
                *(float4*)&b[4] = *(const float4*)&Bs[k * 128 + tx * 8 + 4];
#pragma unroll
                for (int i = 0; i < 8; i++)
#pragma unroll
                    for (int j = 0; j < 8; j++)
                        acc[i][j] = fmaf(a[i], b[j], acc[i][j]);
            }
            __syncthreads();
        }

#pragma unroll
        for (int i = 0; i < 8; i++) {
            int m = bm + ty * 8 + i;
            float4 lo = make_float4(acc[i][0], acc[i][1], acc[i][2], acc[i][3]);
            float4 hi = make_float4(acc[i][4], acc[i][5], acc[i][6], acc[i][7]);
            float* rowp;
            if (HEAD_LAYOUT) {
                int b_ = m >> 11, s_ = m & (SEQ - 1);
                rowp = C + (((size_t)(b_ * NH + bn) * SEQ + s_) * DKH);
            } else {
                rowp = C + (size_t)m * DM + bn * 128;
            }
            *(float4*)(rowp + tx * 8)     = lo;
            *(float4*)(rowp + tx * 8 + 4) = hi;
        }
    }
}

// ---------------------------------------------------------------------------
// Flash attention (unchanged, known-good).
// ---------------------------------------------------------------------------
#define PS_STRIDE 68
#define FLASH_SMEM_FLOATS (8192 + 8192 + 8192 + 64 * PS_STRIDE)
#define FLASH_SMEM_BYTES  (FLASH_SMEM_FLOATS * 4)

__global__ __launch_bounds__(256)
void flash_attn(const float* __restrict__ Q, const float* __restrict__ K,
                const float* __restrict__ V, float* __restrict__ Out) {
    extern __shared__ float smf[];
    float* Qs = smf;
    float* Ks = smf + 8192;
    float* Vs = smf + 16384;
    float* Ps = smf + 24576;

    const int tid = threadIdx.x;
    const int ty  = tid >> 4;
    const int tx  = tid & 15;
    const int s0  = blockIdx.x * 64;
    const int h   = blockIdx.y;
    const int b_  = blockIdx.z;
    const size_t base = (size_t)(b_ * NH + h) * SEQ * DKH;
    const float* Qg = Q + base;
    const float* Kg = K + base;
    const float* Vg = V + base;

    const float qscale = 0.08838834764831845f;

    {
        int r  = tid >> 2;
        int ks = (tid & 3) * 32;
        const float* src = Qg + (size_t)(s0 + r) * DKH + ks;
#pragma unroll
        for (int u = 0; u < 8; u++) {
            float4 v4 = *(const float4*)(src + u * 4);
            Qs[(ks + u * 4 + 0) * 64 + r] = v4.x * qscale;
            Qs[(ks + u * 4 + 1) * 64 + r] = v4.y * qscale;
            Qs[(ks + u * 4 + 2) * 64 + r] = v4.z * qscale;
            Qs[(ks + u * 4 + 3) * 64 + r] = v4.w * qscale;
        }
    }

    float m_i[4], l_i[4];
    ull   o2[4][4];
#pragma unroll
    for (int i = 0; i < 4; i++) {
        m_i[i] = -1e30f; l_i[i] = 0.f;
#pragma unroll
        for (int d = 0; d < 4; d++) o2[i][d] = 0ull;
    }
    __syncthreads();

    for (int j0 = 0; j0 < SEQ; j0 += 64) {
        {
            int r  = tid >> 2;
            int ks = (tid & 3) * 32;
            const float* ksrc = Kg + (size_t)(j0 + r) * DKH + ks;
            const float* vsrc = Vg + (size_t)(j0 + r) * DKH + ks;
#pragma unroll
            for (int u = 0; u < 8; u++) {
                float4 v4 = *(const float4*)(ksrc + u * 4);
                Ks[(ks + u * 4 + 0) * 64 + r] = v4.x;
                Ks[(ks + u * 4 + 1) * 64 + r] = v4.y;
                Ks[(ks + u * 4 + 2) * 64 + r] = v4.z;
                Ks[(ks + u * 4 + 3) * 64 + r] = v4.w;
                *(float4*)&Vs[r * 128 + ks + u * 4] = *(const float4*)(vsrc + u * 4);
            }
        }
        __syncthreads();

        ull sc2[4][2];
#pragma unroll
        for (int i = 0; i < 4; i++) { sc2[i][0] = 0ull; sc2[i][1] = 0ull; }

#pragma unroll 4
        for (int k = 0; k < 128; k++) {
            float4 a = *(const float4*)&Qs[k * 64 + ty * 4];
            ulonglong2 b = *(const ulonglong2*)&Ks[k * 64 + tx * 4];
            float av[4] = {a.x, a.y, a.z, a.w};
#pragma unroll
            for (int i = 0; i < 4; i++) {
                ull ad = dup_f(av[i]);
                fma2(sc2[i][0], ad, b.x);
                fma2(sc2[i][1], ad, b.y);
            }
        }

#pragma unroll
        for (int i = 0; i < 4; i++) {
            float2 s01 = unpk(sc2[i][0]);
            float2 s23 = unpk(sc2[i][1]);
            float sc[4] = {s01.x, s01.y, s23.x, s23.y};
            float rm = fmaxf(fmaxf(sc[0], sc[1]), fmaxf(sc[2], sc[3]));
#pragma unroll
            for (int off = 8; off; off >>= 1)
                rm = fmaxf(rm, __shfl_xor_sync(0xffffffffu, rm, off));
            float mnew = fmaxf(m_i[i], rm);
            float corr = __expf(m_i[i] - mnew);
            float rs = 0.f;
#pragma unroll
            for (int j = 0; j < 4; j++) {
                float p = __expf(sc[j] - mnew);
                sc[j] = p;
                rs += p;
            }
#pragma unroll
            for (int off = 8; off; off >>= 1)
                rs += __shfl_xor_sync(0xffffffffu, rs, off);
            l_i[i] = l_i[i] * corr + rs;
            m_i[i] = mnew;
            ull cd = dup_f(corr);
#pragma unroll
            for (int d = 0; d < 4; d++) mul2(o2[i][d], cd);
            *(float4*)&Ps[(ty * 4 + i) * PS_STRIDE + tx * 4] =
                make_float4(sc[0], sc[1], sc[2], sc[3]);
        }
        __syncthreads();

#pragma unroll 4
        for (int j = 0; j < 64; j++) {
            float p0 = Ps[(ty * 4 + 0) * PS_STRIDE + j];
            float p1 = Ps[(ty * 4 + 1) * PS_STRIDE + j];
            float p2 = Ps[(ty * 4 + 2) * PS_STRIDE + j];
            float p3 = Ps[(ty * 4 + 3) * PS_STRIDE + j];
            ulonglong2 v0 = *(const ulonglong2*)&Vs[j * 128 + tx * 8];
            ulonglong2 v1 = *(const ulonglong2*)&Vs[j * 128 + tx * 8 + 4];
            ull vp[4] = {v0.x, v0.y, v1.x, v1.y};
            ull d0 = dup_f(p0), d1 = dup_f(p1), d2 = dup_f(p2), d3 = dup_f(p3);
#pragma unroll
            for (int d = 0; d < 4; d++) {
                fma2(o2[0][d], d0, vp[d]);
                fma2(o2[1][d], d1, vp[d]);
                fma2(o2[2][d], d2, vp[d]);
                fma2(o2[3][d], d3, vp[d]);
            }
        }
        __syncthreads();
    }

#pragma unroll
    for (int i = 0; i < 4; i++) {
        float inv = 1.f / l_i[i];
        int r = s0 + ty * 4 + i;
        float* dst = Out + ((size_t)(b_ * SEQ + r)) * DM + h * DKH + tx * 8;
        float2 q0 = unpk(o2[i][0]), q1 = unpk(o2[i][1]);
        float2 q2 = unpk(o2[i][2]), q3 = unpk(o2[i][3]);
        *(float4*)dst = make_float4(q0.x * inv, q0.y * inv, q1.x * inv, q1.y * inv);
        *(float4*)(dst + 4) = make_float4(q2.x * inv, q2.y * inv, q3.x * inv, q3.y * inv);
    }
}

// ---------------------------------------------------------------------------
extern "C" void kernel_launch(void* const* d_in, const int* in_sizes, int n_in,
                              void* d_out, int out_size) {
    const float* x  = (const float*)d_in[0];
    const float* wq = (const float*)d_in[1];
    const float* wk = (const float*)d_in[2];
    const float* wv = (const float*)d_in[3];
    const float* wo = (const float*)d_in[4];
    float* out = (float*)d_out;

    float *q, *k, *v, *att;
    bf16 *ah, *al, *wh, *wl;
    cudaGetSymbolAddress((void**)&q,   g_q);
    cudaGetSymbolAddress((void**)&k,   g_k);
    cudaGetSymbolAddress((void**)&v,   g_v);
    cudaGetSymbolAddress((void**)&att, g_att);
    cudaGetSymbolAddress((void**)&ah,  g_ah);
    cudaGetSymbolAddress((void**)&al,  g_al);
    cudaGetSymbolAddress((void**)&wh,  g_wh);
    cudaGetSymbolAddress((void**)&wl,  g_wl);

    cudaFuncSetAttribute(flash_attn,
                         cudaFuncAttributeMaxDynamicSharedMemorySize,
                         FLASH_SMEM_BYTES);
    cudaFuncSetAttribute(gemm_hybrid<0>,
                         cudaFuncAttributeMaxDynamicSharedMemorySize, GEMM_SMEM);
    cudaFuncSetAttribute(gemm_hybrid<1>,
                         cudaFuncAttributeMaxDynamicSharedMemorySize, GEMM_SMEM);

    const int nX4 = MTOT * DM / 4;
    const int nW4 = DM * DM / 4;
    dim3 gg(DM / 128, MTOT / 128);   // (16, 64)

    split_bf16<<<nX4 / 256, 256>>>(x, ah, al, nX4);

    split_bf16<<<nW4 / 256, 256>>>(wq, wh, wl, nW4);
    gemm_hybrid<1><<<gg, 256, GEMM_SMEM>>>(x, wq, ah, al, wh, wl, q);

    split_bf16<<<nW4 / 256, 256>>>(wk, wh, wl, nW4);
    gemm_hybrid<1><<<gg, 256, GEMM_SMEM>>>(x, wk, ah, al, wh, wl, k);

    split_bf16<<<nW4 / 256, 256>>>(wv, wh, wl, nW4);
    gemm_hybrid<1><<<gg, 256, GEMM_SMEM>>>(x, wv, ah, al, wh, wl, v);

    dim3 fg(SEQ / 64, NH, NB);       // (32, 16, 4)
    flash_attn<<<fg, 256, FLASH_SMEM_BYTES>>>(q, k, v, att);

    split_bf16<<<nX4 / 256, 256>>>(att, ah, al, nX4);
    split_bf16<<<nW4 / 256, 256>>>(wo, wh, wl, nW4);
    gemm_hybrid<0><<<gg, 256, GEMM_SMEM>>>(att, wo, ah, al, wh, wl, out);
}

// round 16
// speedup vs baseline: 1.3732x; 1.3732x over previous
#include <cuda_runtime.h>
#include <cuda_fp16.h>
#include <math.h>
#include <stdint.h>

#define DM   2048
#define NH   16
#define DKH  128
#define NB   4
#define SEQ  2048
#define MTOT (NB*SEQ)   // 8192

typedef unsigned long long ull;

// ---- packed f32x2 helpers ---------------------------------------------------
__device__ __forceinline__ ull dup_f(float x) {
    ull d; asm("mov.b64 %0, {%1, %1};" : "=l"(d) : "f"(x)); return d;
}
__device__ __forceinline__ void fma2(ull& d, ull a, ull b) {
    asm("fma.rn.f32x2 %0, %1, %2, %0;" : "+l"(d) : "l"(a), "l"(b));
}
__device__ __forceinline__ void mul2(ull& d, ull a) {
    asm("mul.rn.f32x2 %0, %0, %1;" : "+l"(d) : "l"(a));
}
__device__ __forceinline__ float2 unpk(ull v) {
    float2 f; asm("mov.b64 {%0, %1}, %2;" : "=f"(f.x), "=f"(f.y) : "l"(v)); return f;
}

// ---- HMMA helpers -----------------------------------------------------------
__device__ __forceinline__ uint32_t smem_u32(const void* p) {
    uint32_t a;
    asm("{ .reg .u64 t; cvta.to.shared.u64 t, %1; cvt.u32.u64 %0, t; }"
        : "=r"(a) : "l"(p));
    return a;
}
__device__ __forceinline__ void ldsm4(uint32_t* r, uint32_t addr) {
    asm volatile("ldmatrix.sync.aligned.m8n8.x4.shared.b16 {%0,%1,%2,%3}, [%4];"
                 : "=r"(r[0]), "=r"(r[1]), "=r"(r[2]), "=r"(r[3]) : "r"(addr));
}
__device__ __forceinline__ void mma16816h(float* d, const uint32_t* a,
                                          uint32_t b0, uint32_t b1) {
    asm volatile(
        "mma.sync.aligned.m16n8k16.row.col.f32.f16.f16.f32 "
        "{%0,%1,%2,%3}, {%4,%5,%6,%7}, {%8,%9}, {%0,%1,%2,%3};"
        : "+f"(d[0]), "+f"(d[1]), "+f"(d[2]), "+f"(d[3])
        : "r"(a[0]), "r"(a[1]), "r"(a[2]), "r"(a[3]), "r"(b0), "r"(b1));
}
__device__ __forceinline__ void cp16(uint32_t dst, const void* src) {
    asm volatile("cp.async.cg.shared.global [%0], [%1], 16;"
                 :: "r"(dst), "l"(src));
}
__device__ __forceinline__ void cp_commit() {
    asm volatile("cp.async.commit_group;" ::: "memory");
}
template<int N> __device__ __forceinline__ void cp_wait() {
    asm volatile("cp.async.wait_group %0;" :: "n"(N) : "memory");
}
// smem tile: 128 rows x 64B (32 fp16), 16B-chunk XOR swizzle.
__device__ __forceinline__ uint32_t tile_off(int r, int c) {
    return (uint32_t)(r * 64 + ((c ^ ((r >> 1) & 3)) << 4));
}

// ---- scratch ----------------------------------------------------------------
__device__ float g_q[(size_t)NB*NH*SEQ*DKH];
__device__ float g_k[(size_t)NB*NH*SEQ*DKH];
__device__ float g_v[(size_t)NB*NH*SEQ*DKH];
__device__ float g_att[(size_t)MTOT*DM];
__device__ __half g_ah[(size_t)MTOT*DM];   // A hi (fp16)
__device__ __half g_al[(size_t)MTOT*DM];   // A lo (fp16)
__device__ __half g_wh[(size_t)DM*DM];     // W hi (fp16)

// ---------------------------------------------------------------------------
// Split fp32 -> (hi, lo) fp16 pair.
// ---------------------------------------------------------------------------
__global__ __launch_bounds__(256)
void split_fp16(const float* __restrict__ in, __half* __restrict__ hi,
                __half* __restrict__ lo, int n4) {
    int i = blockIdx.x * 256 + threadIdx.x;
    if (i >= n4) return;
    float4 v = *(const float4*)(in + (size_t)i * 4);
    float vv[4] = {v.x, v.y, v.z, v.w};
    __half h[4], l[4];
#pragma unroll
    for (int j = 0; j < 4; j++) {
        h[j] = __float2half_rn(vv[j]);
        l[j] = __float2half_rn(vv[j] - __half2float(h[j]));
    }
    *(uint2*)(hi + (size_t)i * 4) = *(uint2*)h;
    *(uint2*)(lo + (size_t)i * 4) = *(uint2*)l;
}

// fp32 -> fp16 (hi only, for weights)
__global__ __launch_bounds__(256)
void cvt_fp16(const float* __restrict__ in, __half* __restrict__ hi, int n4) {
    int i = blockIdx.x * 256 + threadIdx.x;
    if (i >= n4) return;
    float4 v = *(const float4*)(in + (size_t)i * 4);
    __half h[4] = {__float2half_rn(v.x), __float2half_rn(v.y),
                   __float2half_rn(v.z), __float2half_rn(v.w)};
    *(uint2*)(hi + (size_t)i * 4) = *(uint2*)h;
}

// ---------------------------------------------------------------------------
// HMMA GEMM, 2-term fp16 split: C = Ahi@Whi^T + Alo@Whi^T.
// CTA 128x128, 8 warps (4m x 2n), warp tile 32x64, K-chunk 32.
// Stage = 3 tiles (Ahi, Alo, Whi) x 8KB = 24KB; 3 stages = 72KB dynamic smem.
// ---------------------------------------------------------------------------
#define STAGE_BYTES 24576
#define NSTAGE      3
#define GEMM_SMEM   (NSTAGE * STAGE_BYTES)
#define NKC         (DM / 32)      // 64

template<int HEAD_LAYOUT>
__global__ __launch_bounds__(256, 2)
void gemm_hmma2(const __half* __restrict__ Ah, const __half* __restrict__ Al,
                const __half* __restrict__ Wh, float* __restrict__ C) {
    extern __shared__ char smg[];
    const uint32_t smb = smem_u32(smg);
    const int tid = threadIdx.x;
    const int wid = tid >> 5;
    const int lid = tid & 31;
    const int wm  = wid & 3;
    const int wn  = wid >> 2;
    const int bn  = blockIdx.x;
    const int bm  = blockIdx.y * 128;

    // load mapping:
    //  ti 0 -> Ahi tile (64 threads, 8 row-iters of stride 16)
    //  ti 1 -> Alo tile (64 threads)
    //  ti 2,3 -> Whi tile (128 threads, 4 row-iters of stride 32)
    const int ti   = tid >> 6;
    const int idxA = tid & 63;
    const int rbA  = idxA >> 2;
    const int lcA  = idxA & 3;
    const int idxW = tid & 127;
    const int rbW  = idxW >> 2;        // 0..31
    const int lcW  = idxW & 3;

    const __half* gA = ((ti == 0) ? Ah : Al) + (size_t)bm * DM;
    const __half* gW = Wh + (size_t)(bn * 128) * DM;

    float acc[2][8][4];
#pragma unroll
    for (int a = 0; a < 2; a++)
#pragma unroll
        for (int b = 0; b < 8; b++)
#pragma unroll
            for (int c = 0; c < 4; c++) acc[a][b][c] = 0.f;

    const int a_row      = wm * 32;
    const int b_rowbase  = wn * 64 + (lid & 7) + ((lid >> 4) << 3);
    const int a_lane_row = (lid & 15);
    const int a_cadd     = (lid >> 4);
    const int b_cadd     = ((lid >> 3) & 1);

    auto issue = [&](int kc) {
        uint32_t sb = smb + (uint32_t)((kc % NSTAGE) * STAGE_BYTES);
        if (ti < 2) {
            uint32_t tb = sb + (uint32_t)(ti * 8192);
            const __half* g = gA + kc * 32 + lcA * 8;
#pragma unroll
            for (int lr = 0; lr < 8; lr++) {
                int row = rbA + lr * 16;
                cp16(tb + tile_off(row, lcA), g + (size_t)row * DM);
            }
        } else {
            uint32_t tb = sb + 16384u;
            const __half* g = gW + kc * 32 + lcW * 8;
#pragma unroll
            for (int lr = 0; lr < 4; lr++) {
                int row = rbW + lr * 32;
                cp16(tb + tile_off(row, lcW), g + (size_t)row * DM);
            }
        }
        cp_commit();
    };

    issue(0);
    issue(1);

    for (int kc = 0; kc < NKC; kc++) {
        if (kc + 2 < NKC) { issue(kc + 2); cp_wait<2>(); }
        else if (kc + 1 < NKC) cp_wait<1>();
        else cp_wait<0>();
        __syncthreads();

        const uint32_t sb = smb + (uint32_t)((kc % NSTAGE) * STAGE_BYTES);
#pragma unroll
        for (int ks = 0; ks < 2; ks++) {
            const int cbase = ks * 2;
            uint32_t ah[2][4], al[2][4];
#pragma unroll
            for (int mt = 0; mt < 2; mt++) {
                int row = a_row + mt * 16 + a_lane_row;
                uint32_t off = tile_off(row, cbase + a_cadd);
                ldsm4(ah[mt], sb + 0 * 8192 + off);
                ldsm4(al[mt], sb + 1 * 8192 + off);
            }
#pragma unroll
            for (int h = 0; h < 2; h++) {
                uint32_t bh[2][4];
#pragma unroll
                for (int p = 0; p < 2; p++) {
                    int row = b_rowbase + (h * 2 + p) * 16;
                    uint32_t off = tile_off(row, cbase + b_cadd);
                    ldsm4(bh[p], sb + 16384u + off);
                }
#pragma unroll
                for (int mt = 0; mt < 2; mt++)
#pragma unroll
                    for (int nt = 0; nt < 4; nt++) {
                        int p = nt >> 1, rr = (nt & 1) * 2;
                        float* d = acc[mt][h * 4 + nt];
                        mma16816h(d, ah[mt], bh[p][rr], bh[p][rr + 1]);
                        mma16816h(d, al[mt], bh[p][rr], bh[p][rr + 1]);
                    }
            }
        }
        __syncthreads();
    }

    const int g = lid >> 2, t4 = lid & 3;
#pragma unroll
    for (int mt = 0; mt < 2; mt++) {
        int m0 = bm + wm * 32 + mt * 16 + g;
#pragma unroll
        for (int half = 0; half < 2; half++) {
            int m = m0 + half * 8;
            float* rowp;
            if (HEAD_LAYOUT) {
                int b_ = m >> 11, s_ = m & (SEQ - 1);
                rowp = C + (((size_t)(b_ * NH + bn) * SEQ + s_) * DKH);
            } else {
                rowp = C + (size_t)m * DM + bn * 128;
            }
#pragma unroll
            for (int j = 0; j < 8; j++) {
                int n = wn * 64 + j * 8 + t4 * 2;
                *(float2*)(rowp + n) = make_float2(acc[mt][j][half * 2],
                                                   acc[mt][j][half * 2 + 1]);
            }
        }
    }
}

// ---------------------------------------------------------------------------
// Flash attention (unchanged, known-good).
// ---------------------------------------------------------------------------
#define PS_STRIDE 68
#define FLASH_SMEM_FLOATS (8192 + 8192 + 8192 + 64 * PS_STRIDE)
#define FLASH_SMEM_BYTES  (FLASH_SMEM_FLOATS * 4)

__global__ __launch_bounds__(256)
void flash_attn(const float* __restrict__ Q, const float* __restrict__ K,
                const float* __restrict__ V, float* __restrict__ Out) {
    extern __shared__ float smf[];
    float* Qs = smf;
    float* Ks = smf + 8192;
    float* Vs = smf + 16384;
    float* Ps = smf + 24576;

    const int tid = threadIdx.x;
    const int ty  = tid >> 4;
    const int tx  = tid & 15;
    const int s0  = blockIdx.x * 64;
    const int h   = blockIdx.y;
    const int b_  = blockIdx.z;
    const size_t base = (size_t)(b_ * NH + h) * SEQ * DKH;
    const float* Qg = Q + base;
    const float* Kg = K + base;
    const float* Vg = V + base;

    const float qscale = 0.08838834764831845f;

    {
        int r  = tid >> 2;
        int ks = (tid & 3) * 32;
        const float* src = Qg + (size_t)(s0 + r) * DKH + ks;
#pragma unroll
        for (int u = 0; u < 8; u++) {
            float4 v4 = *(const float4*)(src + u * 4);
            Qs[(ks + u * 4 + 0) * 64 + r] = v4.x * qscale;
            Qs[(ks + u * 4 + 1) * 64 + r] = v4.y * qscale;
            Qs[(ks + u * 4 + 2) * 64 + r] = v4.z * qscale;
            Qs[(ks + u * 4 + 3) * 64 + r] = v4.w * qscale;
        }
    }

    float m_i[4], l_i[4];
    ull   o2[4][4];
#pragma unroll
    for (int i = 0; i < 4; i++) {
        m_i[i] = -1e30f; l_i[i] = 0.f;
#pragma unroll
        for (int d = 0; d < 4; d++) o2[i][d] = 0ull;
    }
    __syncthreads();

    for (int j0 = 0; j0 < SEQ; j0 += 64) {
        {
            int r  = tid >> 2;
            int ks = (tid & 3) * 32;
            const float* ksrc = Kg + (size_t)(j0 + r) * DKH + ks;
            const float* vsrc = Vg + (size_t)(j0 + r) * DKH + ks;
#pragma unroll
            for (int u = 0; u < 8; u++) {
                float4 v4 = *(const float4*)(ksrc + u * 4);
                Ks[(ks + u * 4 + 0) * 64 + r] = v4.x;
                Ks[(ks + u * 4 + 1) * 64 + r] = v4.y;
                Ks[(ks + u * 4 + 2) * 64 + r] = v4.z;
                Ks[(ks + u * 4 + 3) * 64 + r] = v4.w;
                *(float4*)&Vs[r * 128 + ks + u * 4] = *(const float4*)(vsrc + u * 4);
            }
        }
        __syncthreads();

        ull sc2[4][2];
#pragma unroll
        for (int i = 0; i < 4; i++) { sc2[i][0] = 0ull; sc2[i][1] = 0ull; }

#pragma unroll 4
        for (int k = 0; k < 128; k++) {
            float4 a = *(const float4*)&Qs[k * 64 + ty * 4];
            ulonglong2 b = *(const ulonglong2*)&Ks[k * 64 + tx * 4];
            float av[4] = {a.x, a.y, a.z, a.w};
#pragma unroll
            for (int i = 0; i < 4; i++) {
                ull ad = dup_f(av[i]);
                fma2(sc2[i][0], ad, b.x);
                fma2(sc2[i][1], ad, b.y);
            }
        }

#pragma unroll
        for (int i = 0; i < 4; i++) {
            float2 s01 = unpk(sc2[i][0]);
            float2 s23 = unpk(sc2[i][1]);
            float sc[4] = {s01.x, s01.y, s23.x, s23.y};
            float rm = fmaxf(fmaxf(sc[0], sc[1]), fmaxf(sc[2], sc[3]));
#pragma unroll
            for (int off = 8; off; off >>= 1)
                rm = fmaxf(rm, __shfl_xor_sync(0xffffffffu, rm, off));
            float mnew = fmaxf(m_i[i], rm);
            float corr = __expf(m_i[i] - mnew);
            float rs = 0.f;
#pragma unroll
            for (int j = 0; j < 4; j++) {
                float p = __expf(sc[j] - mnew);
                sc[j] = p;
                rs += p;
            }
#pragma unroll
            for (int off = 8; off; off >>= 1)
                rs += __shfl_xor_sync(0xffffffffu, rs, off);
            l_i[i] = l_i[i] * corr + rs;
            m_i[i] = mnew;
            ull cd = dup_f(corr);
#pragma unroll
            for (int d = 0; d < 4; d++) mul2(o2[i][d], cd);
            *(float4*)&Ps[(ty * 4 + i) * PS_STRIDE + tx * 4] =
                make_float4(sc[0], sc[1], sc[2], sc[3]);
        }
        __syncthreads();

#pragma unroll 4
        for (int j = 0; j < 64; j++) {
            float p0 = Ps[(ty * 4 + 0) * PS_STRIDE + j];
            float p1 = Ps[(ty * 4 + 1) * PS_STRIDE + j];
            float p2 = Ps[(ty * 4 + 2) * PS_STRIDE + j];
            float p3 = Ps[(ty * 4 + 3) * PS_STRIDE + j];
            ulonglong2 v0 = *(const ulonglong2*)&Vs[j * 128 + tx * 8];
            ulonglong2 v1 = *(const ulonglong2*)&Vs[j * 128 + tx * 8 + 4];
            ull vp[4] = {v0.x, v0.y, v1.x, v1.y};
            ull d0 = dup_f(p0), d1 = dup_f(p1), d2 = dup_f(p2), d3 = dup_f(p3);
#pragma unroll
            for (int d = 0; d < 4; d++) {
                fma2(o2[0][d], d0, vp[d]);
                fma2(o2[1][d], d1, vp[d]);
                fma2(o2[2][d], d2, vp[d]);
                fma2(o2[3][d], d3, vp[d]);
            }
        }
        __syncthreads();
    }

#pragma unroll
    for (int i = 0; i < 4; i++) {
        float inv = 1.f / l_i[i];
        int r = s0 + ty * 4 + i;
        float* dst = Out + ((size_t)(b_ * SEQ + r)) * DM + h * DKH + tx * 8;
        float2 q0 = unpk(o2[i][0]), q1 = unpk(o2[i][1]);
        float2 q2 = unpk(o2[i][2]), q3 = unpk(o2[i][3]);
        *(float4*)dst = make_float4(q0.x * inv, q0.y * inv, q1.x * inv, q1.y * inv);
        *(float4*)(dst + 4) = make_float4(q2.x * inv, q2.y * inv, q3.x * inv, q3.y * inv);
    }
}

// ---------------------------------------------------------------------------
extern "C" void kernel_launch(void* const* d_in, const int* in_sizes, int n_in,
                              void* d_out, int out_size) {
    const float* x  = (const float*)d_in[0];
    const float* wq = (const float*)d_in[1];
    const float* wk = (const float*)d_in[2];
    const float* wv = (const float*)d_in[3];
    const float* wo = (const float*)d_in[4];
    float* out = (float*)d_out;

    float *q, *k, *v, *att;
    __half *ah, *al, *wh;
    cudaGetSymbolAddress((void**)&q,   g_q);
    cudaGetSymbolAddress((void**)&k,   g_k);
    cudaGetSymbolAddress((void**)&v,   g_v);
    cudaGetSymbolAddress((void**)&att, g_att);
    cudaGetSymbolAddress((void**)&ah,  g_ah);
    cudaGetSymbolAddress((void**)&al,  g_al);
    cudaGetSymbolAddress((void**)&wh,  g_wh);

    cudaFuncSetAttribute(flash_attn,
                         cudaFuncAttributeMaxDynamicSharedMemorySize,
                         FLASH_SMEM_BYTES);
    cudaFuncSetAttribute(gemm_hmma2<0>,
                         cudaFuncAttributeMaxDynamicSharedMemorySize, GEMM_SMEM);
    cudaFuncSetAttribute(gemm_hmma2<1>,
                         cudaFuncAttributeMaxDynamicSharedMemorySize, GEMM_SMEM);

    const int nX4 = MTOT * DM / 4;
    const int nW4 = DM * DM / 4;
    dim3 gg(DM / 128, MTOT / 128);   // (16, 64)

    split_fp16<<<nX4 / 256, 256>>>(x, ah, al, nX4);

    cvt_fp16<<<nW4 / 256, 256>>>(wq, wh, nW4);
    gemm_hmma2<1><<<gg, 256, GEMM_SMEM>>>(ah, al, wh, q);

    cvt_fp16<<<nW4 / 256, 256>>>(wk, wh, nW4);
    gemm_hmma2<1><<<gg, 256, GEMM_SMEM>>>(ah, al, wh, k);

    cvt_fp16<<<nW4 / 256, 256>>>(wv, wh, nW4);
    gemm_hmma2<1><<<gg, 256, GEMM_SMEM>>>(ah, al, wh, v);

    dim3 fg(SEQ / 64, NH, NB);       // (32, 16, 4)
    flash_attn<<<fg, 256, FLASH_SMEM_BYTES>>>(q, k, v, att);

    split_fp16<<<nX4 / 256, 256>>>(att, ah, al, nX4);
    cvt_fp16<<<nW4 / 256, 256>>>(wo, wh, nW4);
    gemm_hmma2<0><<<gg, 256, GEMM_SMEM>>>(ah, al, wh, out);
}